// round 1
// baseline (speedup 1.0000x reference)
#include <cuda_runtime.h>
#include <cstdint>

#define BB 512
#define NN 128
#define DD 512
#define BN (BB * NN)   // 65536

// ---------------- device scratch (allocation-free rule: __device__ globals) ----
__device__ float g_aggr[BN * DD];   // 128 MB
__device__ float g_x1[BN * DD];     // 128 MB
__device__ float g_x2[BN * DD];     // 128 MB
__device__ int   g_idx[BN * 3];
__device__ float g_cnt[BN];
__device__ float g_uv[BB * 2 * DD];
__device__ float g_M[4 * DD];       // Ml(o=0), Ml(o=1), Mr(o=0), Mr(o=1)

// ---------------------------------------------------------------------------
// kNN: per batch compute cosine Gram and top-3 indices (self included).
// grid = (2, B) : blockIdx.x selects i-half (64 rows), blockIdx.y = batch.
// 256 threads. One shared X-tile serves both Gram operands.
// ---------------------------------------------------------------------------
__global__ void __launch_bounds__(256) knn_kernel(const float* __restrict__ x,
                                                  int* __restrict__ idx_out) {
    __shared__ float Xs[16][128];
    __shared__ float simS[64][129];   // padded: stride 129 avoids bank conflicts on column scans
    __shared__ float sinv[128];

    const int b  = blockIdx.y;
    const int i0 = blockIdx.x * 64;
    const int tid = threadIdx.x;
    const float* xb = x + (size_t)b * NN * DD;

    // inverse norms for all 128 rows
    const int warp = tid >> 5, lane = tid & 31;
    for (int r = warp; r < NN; r += 8) {
        float s = 0.f;
        const float* row = xb + (size_t)r * DD;
        #pragma unroll 4
        for (int d = lane; d < DD; d += 32) { float v = row[d]; s += v * v; }
        #pragma unroll
        for (int off = 16; off; off >>= 1) s += __shfl_xor_sync(0xffffffffu, s, off);
        if (lane == 0) sinv[r] = rsqrtf(s + 1e-12f);
    }
    __syncthreads();

    const int tx = tid & 15, ty = tid >> 4;
    float acc[4][8];
    #pragma unroll
    for (int r = 0; r < 4; ++r)
        #pragma unroll
        for (int c = 0; c < 8; ++c) acc[r][c] = 0.f;

    for (int k0 = 0; k0 < DD; k0 += 16) {
        #pragma unroll
        for (int q = 0; q < 2; ++q) {
            int lin = tid + q * 256;          // 0..511
            int j   = lin >> 2;               // 0..127
            int kq  = (lin & 3) << 2;         // 0,4,8,12
            float4 v = *(const float4*)(xb + (size_t)j * DD + k0 + kq);
            Xs[kq + 0][j] = v.x; Xs[kq + 1][j] = v.y;
            Xs[kq + 2][j] = v.z; Xs[kq + 3][j] = v.w;
        }
        __syncthreads();
        #pragma unroll
        for (int k = 0; k < 16; ++k) {
            float a[4], bv[8];
            #pragma unroll
            for (int r = 0; r < 4; ++r) a[r] = Xs[k][i0 + ty * 4 + r];
            #pragma unroll
            for (int c = 0; c < 8; ++c) bv[c] = Xs[k][tx * 8 + c];
            #pragma unroll
            for (int r = 0; r < 4; ++r)
                #pragma unroll
                for (int c = 0; c < 8; ++c) acc[r][c] += a[r] * bv[c];
        }
        __syncthreads();
    }

    #pragma unroll
    for (int r = 0; r < 4; ++r) {
        float si = sinv[i0 + ty * 4 + r];
        #pragma unroll
        for (int c = 0; c < 8; ++c)
            simS[ty * 4 + r][tx * 8 + c] = acc[r][c] * si * sinv[tx * 8 + c];
    }
    __syncthreads();

    if (tid < 64) {
        const int i = i0 + tid;
        int b0 = -1, b1 = -1;
        #pragma unroll
        for (int t = 0; t < 3; ++t) {
            float bvv = -1e30f; int bi = -1;
            for (int j = 0; j < NN; ++j) {
                if (j == b0 || j == b1) continue;
                float v = simS[tid][j];
                if (v > bvv) { bvv = v; bi = j; }   // strict '>' == stable tie-break (lowest index)
            }
            idx_out[((size_t)b * NN + i) * 3 + t] = bi;
            if (t == 0) b0 = bi; else if (t == 1) b1 = bi;
        }
    }
}

// ---------------------------------------------------------------------------
// in-degree counts per batch (for the layer-3 algebraic reduction)
// ---------------------------------------------------------------------------
__global__ void cnt_kernel(const int* __restrict__ idx, float* __restrict__ cnt) {
    __shared__ int c[NN];
    const int b = blockIdx.x, t = threadIdx.x;   // 128 threads
    c[t] = 0;
    __syncthreads();
    const int* ib = idx + (size_t)b * NN * 3 + (size_t)t * 3;
    atomicAdd(&c[ib[0]], 1);
    atomicAdd(&c[ib[1]], 1);
    atomicAdd(&c[ib[2]], 1);
    __syncthreads();
    cnt[(size_t)b * NN + t] = (float)c[t];
}

// ---------------------------------------------------------------------------
// aggr[m, :] = mean of 3 neighbor rows. grid = BN blocks, 128 threads (float4).
// ---------------------------------------------------------------------------
__global__ void gather_kernel(const float* __restrict__ x, const int* __restrict__ idx,
                              float* __restrict__ out) {
    const int m = blockIdx.x;          // b*N + n
    const int b = m >> 7;
    const int* ip = idx + (size_t)m * 3;
    const int j0 = ip[0], j1 = ip[1], j2 = ip[2];
    const float4* r0 = (const float4*)(x + ((size_t)b * NN + j0) * DD);
    const float4* r1 = (const float4*)(x + ((size_t)b * NN + j1) * DD);
    const float4* r2 = (const float4*)(x + ((size_t)b * NN + j2) * DD);
    const int t = threadIdx.x;         // 128 threads * float4 = 512
    float4 v0 = r0[t], v1 = r1[t], v2 = r2[t];
    const float inv3 = 1.f / 3.f;
    float4 r;
    r.x = (v0.x + v1.x + v2.x) * inv3;
    r.y = (v0.y + v1.y + v2.y) * inv3;
    r.z = (v0.z + v1.z + v2.z) * inv3;
    r.w = (v0.w + v1.w + v2.w) * inv3;
    ((float4*)(out + (size_t)m * DD))[t] = r;
}

// ---------------------------------------------------------------------------
// Fused SAGE GEMM: out = leaky?( A1*W1^T + A2*W2^T + bias )
// M=65536, N=512, effective K=1024. 128x128 C tile, 256 threads, 8x8/thread.
// ---------------------------------------------------------------------------
__global__ void __launch_bounds__(256) sage_gemm(const float* __restrict__ A1,
                                                 const float* __restrict__ A2,
                                                 const float* __restrict__ W1,
                                                 const float* __restrict__ W2,
                                                 const float* __restrict__ bias,
                                                 float* __restrict__ out, int leaky) {
    __shared__ float As[16][128];
    __shared__ float Bs[16][128];
    const int tid = threadIdx.x;
    const int tx = tid & 15, ty = tid >> 4;
    const int mBase = blockIdx.y * 128;
    const int oBase = blockIdx.x * 128;

    float acc[8][8];
    #pragma unroll
    for (int r = 0; r < 8; ++r)
        #pragma unroll
        for (int c = 0; c < 8; ++c) acc[r][c] = 0.f;

    #pragma unroll 1
    for (int part = 0; part < 2; ++part) {
        const float* A = part ? A2 : A1;
        const float* W = part ? W2 : W1;
        #pragma unroll 1
        for (int k0 = 0; k0 < DD; k0 += 16) {
            #pragma unroll
            for (int q = 0; q < 2; ++q) {
                int lin = tid + q * 256;
                int mm  = lin >> 2;
                int kq  = (lin & 3) << 2;
                float4 va = *(const float4*)(A + (size_t)(mBase + mm) * DD + k0 + kq);
                As[kq + 0][mm] = va.x; As[kq + 1][mm] = va.y;
                As[kq + 2][mm] = va.z; As[kq + 3][mm] = va.w;
                float4 vb = *(const float4*)(W + (size_t)(oBase + mm) * DD + k0 + kq);
                Bs[kq + 0][mm] = vb.x; Bs[kq + 1][mm] = vb.y;
                Bs[kq + 2][mm] = vb.z; Bs[kq + 3][mm] = vb.w;
            }
            __syncthreads();
            #pragma unroll
            for (int k = 0; k < 16; ++k) {
                float4 a0 = *(const float4*)&As[k][ty * 8];
                float4 a1 = *(const float4*)&As[k][ty * 8 + 4];
                float4 b0 = *(const float4*)&Bs[k][tx * 8];
                float4 b1 = *(const float4*)&Bs[k][tx * 8 + 4];
                float av[8] = {a0.x, a0.y, a0.z, a0.w, a1.x, a1.y, a1.z, a1.w};
                float bv[8] = {b0.x, b0.y, b0.z, b0.w, b1.x, b1.y, b1.z, b1.w};
                #pragma unroll
                for (int r = 0; r < 8; ++r)
                    #pragma unroll
                    for (int c = 0; c < 8; ++c) acc[r][c] += av[r] * bv[c];
            }
            __syncthreads();
        }
    }

    #pragma unroll
    for (int r = 0; r < 8; ++r) {
        const int m = mBase + ty * 8 + r;
        float* orow = out + (size_t)m * DD + oBase + tx * 8;
        float4 v0, v1;
        float tmp[8];
        #pragma unroll
        for (int c = 0; c < 8; ++c) {
            float v = acc[r][c] + bias[oBase + tx * 8 + c];
            if (leaky) v = (v >= 0.f) ? v : 0.2f * v;
            tmp[c] = v;
        }
        v0.x = tmp[0]; v0.y = tmp[1]; v0.z = tmp[2]; v0.w = tmp[3];
        v1.x = tmp[4]; v1.y = tmp[5]; v1.z = tmp[6]; v1.w = tmp[7];
        *(float4*)(orow)     = v0;
        *(float4*)(orow + 4) = v1;
    }
}

// ---------------------------------------------------------------------------
// M[which][o][d] = sum_e wc[o,e] * W_which[e,d]   (Wc @ W3l, Wc @ W3r)
// grid = 4 blocks (which*2+o), 512 threads.
// ---------------------------------------------------------------------------
__global__ void mlmr_kernel(const float* __restrict__ wc, const float* __restrict__ w3l,
                            const float* __restrict__ w3r, float* __restrict__ M) {
    const int o = blockIdx.x & 1, which = blockIdx.x >> 1;
    const float* W = which ? w3r : w3l;
    const int d = threadIdx.x;  // 512
    float s = 0.f;
    #pragma unroll 8
    for (int e = 0; e < DD; ++e) s += wc[o * DD + e] * W[(size_t)e * DD + d];
    M[which * 2 * DD + o * DD + d] = s;
}

// ---------------------------------------------------------------------------
// u[b,d] = sum_i cnt[b,i]*x2[b,i,d] / (3N);  v[b,d] = mean_i x2[b,i,d]
// ---------------------------------------------------------------------------
__global__ void uv_kernel(const float* __restrict__ x2, const float* __restrict__ cnt,
                          float* __restrict__ uv) {
    __shared__ float cs[NN];
    const int b = blockIdx.x, t = threadIdx.x;   // 512 threads
    if (t < NN) cs[t] = cnt[(size_t)b * NN + t];
    __syncthreads();
    const float* xb = x2 + (size_t)b * NN * DD;
    float u = 0.f, v = 0.f;
    #pragma unroll 4
    for (int i = 0; i < NN; ++i) {
        float val = xb[(size_t)i * DD + t];
        v += val;
        u += cs[i] * val;
    }
    uv[(size_t)b * 2 * DD + t]      = u * (1.f / (3.f * (float)NN));
    uv[(size_t)b * 2 * DD + DD + t] = v * (1.f / (float)NN);
}

// ---------------------------------------------------------------------------
// out[b,o] = sum_d u*Ml[o,d] + v*Mr[o,d] + wc[o,d]*b3l[d]   (+ bc[o])
// ---------------------------------------------------------------------------
__global__ void final_kernel(const float* __restrict__ uv, const float* __restrict__ M,
                             const float* __restrict__ wc, const float* __restrict__ b3l,
                             const float* __restrict__ bc, float* __restrict__ out) {
    const int b = blockIdx.x, t = threadIdx.x;   // 512 threads
    const float u = uv[(size_t)b * 2 * DD + t];
    const float v = uv[(size_t)b * 2 * DD + DD + t];
    const float bl = b3l[t];
    float s0 = u * M[t]       + v * M[2 * DD + t]       + wc[t] * bl;
    float s1 = u * M[DD + t]  + v * M[3 * DD + t]       + wc[DD + t] * bl;
    #pragma unroll
    for (int off = 16; off; off >>= 1) {
        s0 += __shfl_xor_sync(0xffffffffu, s0, off);
        s1 += __shfl_xor_sync(0xffffffffu, s1, off);
    }
    __shared__ float r0[16], r1[16];
    const int warp = t >> 5, lane = t & 31;
    if (lane == 0) { r0[warp] = s0; r1[warp] = s1; }
    __syncthreads();
    if (t == 0) {
        float t0 = 0.f, t1 = 0.f;
        #pragma unroll
        for (int w = 0; w < 16; ++w) { t0 += r0[w]; t1 += r1[w]; }
        out[b * 2 + 0] = t0 + bc[0];
        out[b * 2 + 1] = t1 + bc[1];
    }
}

// ---------------------------------------------------------------------------
extern "C" void kernel_launch(void* const* d_in, const int* in_sizes, int n_in,
                              void* d_out, int out_size) {
    const float* enc = (const float*)d_in[0];
    const float* w1l = (const float*)d_in[1];
    const float* b1l = (const float*)d_in[2];
    const float* w1r = (const float*)d_in[3];
    const float* w2l = (const float*)d_in[4];
    const float* b2l = (const float*)d_in[5];
    const float* w2r = (const float*)d_in[6];
    const float* w3l = (const float*)d_in[7];
    const float* b3l = (const float*)d_in[8];
    const float* w3r = (const float*)d_in[9];
    const float* wc  = (const float*)d_in[10];
    const float* bc  = (const float*)d_in[11];
    float* out = (float*)d_out;

    float *aggr, *x1, *x2, *cntp, *uvp, *Mp;
    int* idxp;
    cudaGetSymbolAddress((void**)&aggr, g_aggr);
    cudaGetSymbolAddress((void**)&x1,   g_x1);
    cudaGetSymbolAddress((void**)&x2,   g_x2);
    cudaGetSymbolAddress((void**)&idxp, g_idx);
    cudaGetSymbolAddress((void**)&cntp, g_cnt);
    cudaGetSymbolAddress((void**)&uvp,  g_uv);
    cudaGetSymbolAddress((void**)&Mp,   g_M);

    // kNN graph
    knn_kernel<<<dim3(2, BB), 256>>>(enc, idxp);
    cnt_kernel<<<BB, NN>>>(idxp, cntp);

    // layer 1 (leaky)
    gather_kernel<<<BN, 128>>>(enc, idxp, aggr);
    sage_gemm<<<dim3(4, BN / 128), 256>>>(aggr, enc, w1l, w1r, b1l, x1, 1);

    // layer 2 (leaky)
    gather_kernel<<<BN, 128>>>(x1, idxp, aggr);
    sage_gemm<<<dim3(4, BN / 128), 256>>>(aggr, x1, w2l, w2r, b2l, x2, 1);

    // layer 3 + mean-pool + classifier, algebraically collapsed
    mlmr_kernel<<<4, DD>>>(wc, w3l, w3r, Mp);
    uv_kernel<<<BB, DD>>>(x2, cntp, uvp);
    final_kernel<<<BB, DD>>>(uvp, Mp, wc, b3l, bc, out);
}

// round 3
// speedup vs baseline: 1.5032x; 1.5032x over previous
#include <cuda_runtime.h>
#include <cstdint>

#define BB 512
#define NN 128
#define DD 512
#define BN (BB * NN)   // 65536

// ---------------- device scratch (allocation-free rule: __device__ globals) ----
__device__ float g_x1[BN * DD];     // 128 MB
__device__ float g_x2[BN * DD];     // 128 MB
__device__ int   g_idx[BN * 3];
__device__ float g_cnt[BN];
__device__ float g_uv[BB * 2 * DD];
__device__ float g_M[4 * DD];

// ---------------------------------------------------------------------------
__device__ __forceinline__ uint32_t f2tf32(float f) {
    uint32_t r;
    asm("cvt.rna.tf32.f32 %0, %1;" : "=r"(r) : "f"(f));
    return r;
}

__device__ __forceinline__ void mma_tf32(float* c, const uint32_t* a, const uint32_t* b) {
    asm volatile(
        "mma.sync.aligned.m16n8k8.row.col.f32.tf32.tf32.f32 "
        "{%0,%1,%2,%3}, {%4,%5,%6,%7}, {%8,%9}, {%0,%1,%2,%3};"
        : "+f"(c[0]), "+f"(c[1]), "+f"(c[2]), "+f"(c[3])
        : "r"(a[0]), "r"(a[1]), "r"(a[2]), "r"(a[3]), "r"(b[0]), "r"(b[1]));
}

// ---------------------------------------------------------------------------
// kNN: per batch compute cosine Gram and top-3 indices (self included).
// ---------------------------------------------------------------------------
__global__ void __launch_bounds__(256) knn_kernel(const float* __restrict__ x,
                                                  int* __restrict__ idx_out) {
    __shared__ float Xs[16][128];
    __shared__ float simS[64][129];
    __shared__ float sinv[128];

    const int b  = blockIdx.y;
    const int i0 = blockIdx.x * 64;
    const int tid = threadIdx.x;
    const float* xb = x + (size_t)b * NN * DD;

    const int warp = tid >> 5, lane = tid & 31;
    for (int r = warp; r < NN; r += 8) {
        float s = 0.f;
        const float* row = xb + (size_t)r * DD;
        #pragma unroll 4
        for (int d = lane; d < DD; d += 32) { float v = row[d]; s += v * v; }
        #pragma unroll
        for (int off = 16; off; off >>= 1) s += __shfl_xor_sync(0xffffffffu, s, off);
        if (lane == 0) sinv[r] = rsqrtf(s + 1e-12f);
    }
    __syncthreads();

    const int tx = tid & 15, ty = tid >> 4;
    float acc[4][8];
    #pragma unroll
    for (int r = 0; r < 4; ++r)
        #pragma unroll
        for (int c = 0; c < 8; ++c) acc[r][c] = 0.f;

    for (int k0 = 0; k0 < DD; k0 += 16) {
        #pragma unroll
        for (int q = 0; q < 2; ++q) {
            int lin = tid + q * 256;
            int j   = lin >> 2;
            int kq  = (lin & 3) << 2;
            float4 v = *(const float4*)(xb + (size_t)j * DD + k0 + kq);
            Xs[kq + 0][j] = v.x; Xs[kq + 1][j] = v.y;
            Xs[kq + 2][j] = v.z; Xs[kq + 3][j] = v.w;
        }
        __syncthreads();
        #pragma unroll
        for (int k = 0; k < 16; ++k) {
            float a[4], bv[8];
            #pragma unroll
            for (int r = 0; r < 4; ++r) a[r] = Xs[k][i0 + ty * 4 + r];
            #pragma unroll
            for (int c = 0; c < 8; ++c) bv[c] = Xs[k][tx * 8 + c];
            #pragma unroll
            for (int r = 0; r < 4; ++r)
                #pragma unroll
                for (int c = 0; c < 8; ++c) acc[r][c] += a[r] * bv[c];
        }
        __syncthreads();
    }

    #pragma unroll
    for (int r = 0; r < 4; ++r) {
        float si = sinv[i0 + ty * 4 + r];
        #pragma unroll
        for (int c = 0; c < 8; ++c)
            simS[ty * 4 + r][tx * 8 + c] = acc[r][c] * si * sinv[tx * 8 + c];
    }
    __syncthreads();

    if (tid < 64) {
        const int i = i0 + tid;
        int b0 = -1, b1 = -1;
        #pragma unroll
        for (int t = 0; t < 3; ++t) {
            float bvv = -1e30f; int bi = -1;
            for (int j = 0; j < NN; ++j) {
                if (j == b0 || j == b1) continue;
                float v = simS[tid][j];
                if (v > bvv) { bvv = v; bi = j; }
            }
            idx_out[((size_t)b * NN + i) * 3 + t] = bi;
            if (t == 0) b0 = bi; else if (t == 1) b1 = bi;
        }
    }
}

// ---------------------------------------------------------------------------
__global__ void cnt_kernel(const int* __restrict__ idx, float* __restrict__ cnt) {
    __shared__ int c[NN];
    const int b = blockIdx.x, t = threadIdx.x;
    c[t] = 0;
    __syncthreads();
    const int* ib = idx + (size_t)b * NN * 3 + (size_t)t * 3;
    atomicAdd(&c[ib[0]], 1);
    atomicAdd(&c[ib[1]], 1);
    atomicAdd(&c[ib[2]], 1);
    __syncthreads();
    cnt[(size_t)b * NN + t] = (float)c[t];
}

// ---------------------------------------------------------------------------
// tf32 mma.sync fused SAGE layer:
//   out[m,:] = act( mean3(x[nbrs(m)]) @ Wl^T + x[m] @ Wr^T + bias )
// CTA = 128(M, one batch) x 128(N). 8 warps 2x4, warp tile 64x32, m16n8k8.
// K fused 2*512, chunks of 32, register-prefetch single-smem-buffer pipeline.
// ---------------------------------------------------------------------------
__global__ void __launch_bounds__(256, 1) sage_mma(const float* __restrict__ Xsrc,
                                                   const int* __restrict__ idx,
                                                   const float* __restrict__ Wl,
                                                   const float* __restrict__ Wr,
                                                   const float* __restrict__ bias,
                                                   float* __restrict__ out, int leaky) {
    __shared__ float As[128][36];   // [m][k], pad 4 -> conflict-free frags
    __shared__ float Bs[128][36];   // [n][k]
    __shared__ int   idxs[NN * 3];

    const int tid  = threadIdx.x;
    const int wid  = tid >> 5, lane = tid & 31;
    const int warpM = wid & 1;          // 0..1 -> 64 rows
    const int warpN = wid >> 1;         // 0..3 -> 32 cols
    const int oBase = blockIdx.x * 128;
    const int b     = blockIdx.y;       // M tile == batch
    const float* xb = Xsrc + (size_t)b * NN * DD;

    for (int t = tid; t < NN * 3; t += 256) idxs[t] = idx[(size_t)b * NN * 3 + t];
    __syncthreads();

    // producer mapping: each thread owns 16 A floats + 16 B floats per chunk
    const int prow = tid >> 1;              // 0..127
    const int pkq  = (tid & 1) * 16;        // 0 / 16
    const int j0 = idxs[prow * 3], j1 = idxs[prow * 3 + 1], j2 = idxs[prow * 3 + 2];
    const float inv3 = 1.f / 3.f;

    float acc[4][4][4];
    #pragma unroll
    for (int i = 0; i < 4; ++i)
        #pragma unroll
        for (int j = 0; j < 4; ++j)
            #pragma unroll
            for (int r = 0; r < 4; ++r) acc[i][j][r] = 0.f;

    float4 pa[4], pb[4];

    // prefetch chunk 0 (part 0 = gather, k0 = 0)
    {
        const float* q0 = xb + (size_t)j0 * DD + pkq;
        const float* q1 = xb + (size_t)j1 * DD + pkq;
        const float* q2 = xb + (size_t)j2 * DD + pkq;
        #pragma unroll
        for (int jj = 0; jj < 4; ++jj) {
            float4 a = *(const float4*)(q0 + jj * 4);
            float4 c = *(const float4*)(q1 + jj * 4);
            float4 d = *(const float4*)(q2 + jj * 4);
            pa[jj].x = (a.x + c.x + d.x) * inv3;
            pa[jj].y = (a.y + c.y + d.y) * inv3;
            pa[jj].z = (a.z + c.z + d.z) * inv3;
            pa[jj].w = (a.w + c.w + d.w) * inv3;
            pb[jj] = *(const float4*)(Wl + (size_t)(oBase + prow) * DD + pkq + jj * 4);
        }
    }

    #pragma unroll 1
    for (int it = 0; it < 32; ++it) {
        __syncthreads();   // consumers done with smem
        #pragma unroll
        for (int jj = 0; jj < 4; ++jj) {
            *(float4*)&As[prow][pkq + jj * 4] = pa[jj];
            *(float4*)&Bs[prow][pkq + jj * 4] = pb[jj];
        }
        __syncthreads();   // smem ready

        // prefetch next chunk (overlaps with mma below)
        if (it < 31) {
            const int nit  = it + 1;
            const int part = nit >> 4;
            const int k0   = (nit & 15) * 32;
            const float* W = part ? Wr : Wl;
            if (part == 0) {
                const float* q0 = xb + (size_t)j0 * DD + k0 + pkq;
                const float* q1 = xb + (size_t)j1 * DD + k0 + pkq;
                const float* q2 = xb + (size_t)j2 * DD + k0 + pkq;
                #pragma unroll
                for (int jj = 0; jj < 4; ++jj) {
                    float4 a = *(const float4*)(q0 + jj * 4);
                    float4 c = *(const float4*)(q1 + jj * 4);
                    float4 d = *(const float4*)(q2 + jj * 4);
                    pa[jj].x = (a.x + c.x + d.x) * inv3;
                    pa[jj].y = (a.y + c.y + d.y) * inv3;
                    pa[jj].z = (a.z + c.z + d.z) * inv3;
                    pa[jj].w = (a.w + c.w + d.w) * inv3;
                }
            } else {
                const float* q = xb + (size_t)prow * DD + k0 + pkq;
                #pragma unroll
                for (int jj = 0; jj < 4; ++jj) pa[jj] = *(const float4*)(q + jj * 4);
            }
            #pragma unroll
            for (int jj = 0; jj < 4; ++jj)
                pb[jj] = *(const float4*)(W + (size_t)(oBase + prow) * DD + k0 + pkq + jj * 4);
        }

        // consume: 4 k-steps of 8
        const int g = lane >> 2, tg = lane & 3;
        #pragma unroll
        for (int ks = 0; ks < 4; ++ks) {
            const int kk = ks * 8 + tg;
            uint32_t af[4][4], bf[4][2];
            #pragma unroll
            for (int mf = 0; mf < 4; ++mf) {
                const int r = warpM * 64 + mf * 16 + g;
                af[mf][0] = f2tf32(As[r][kk]);
                af[mf][1] = f2tf32(As[r + 8][kk]);
                af[mf][2] = f2tf32(As[r][kk + 4]);
                af[mf][3] = f2tf32(As[r + 8][kk + 4]);
            }
            #pragma unroll
            for (int nf = 0; nf < 4; ++nf) {
                const int c = warpN * 32 + nf * 8 + g;
                bf[nf][0] = f2tf32(Bs[c][kk]);
                bf[nf][1] = f2tf32(Bs[c][kk + 4]);
            }
            #pragma unroll
            for (int mf = 0; mf < 4; ++mf)
                #pragma unroll
                for (int nf = 0; nf < 4; ++nf)
                    mma_tf32(acc[mf][nf], af[mf], bf[nf]);
        }
    }

    // epilogue
    const int g = lane >> 2, tg = lane & 3;
    #pragma unroll
    for (int mf = 0; mf < 4; ++mf) {
        const int row0 = b * NN + warpM * 64 + mf * 16 + g;
        #pragma unroll
        for (int nf = 0; nf < 4; ++nf) {
            const int col = oBase + warpN * 32 + nf * 8 + tg * 2;
            const float b0 = bias[col], b1 = bias[col + 1];
            float v0 = acc[mf][nf][0] + b0;
            float v1 = acc[mf][nf][1] + b1;
            float v2 = acc[mf][nf][2] + b0;
            float v3 = acc[mf][nf][3] + b1;
            if (leaky) {
                v0 = v0 >= 0.f ? v0 : 0.2f * v0;
                v1 = v1 >= 0.f ? v1 : 0.2f * v1;
                v2 = v2 >= 0.f ? v2 : 0.2f * v2;
                v3 = v3 >= 0.f ? v3 : 0.2f * v3;
            }
            float2 lo; lo.x = v0; lo.y = v1;
            float2 hi; hi.x = v2; hi.y = v3;
            *(float2*)&out[(size_t)row0 * DD + col]       = lo;
            *(float2*)&out[(size_t)(row0 + 8) * DD + col] = hi;
        }
    }
}

// ---------------------------------------------------------------------------
__global__ void mlmr_kernel(const float* __restrict__ wc, const float* __restrict__ w3l,
                            const float* __restrict__ w3r, float* __restrict__ M) {
    const int o = blockIdx.x & 1, which = blockIdx.x >> 1;
    const float* W = which ? w3r : w3l;
    const int d = threadIdx.x;
    float s = 0.f;
    #pragma unroll 8
    for (int e = 0; e < DD; ++e) s += wc[o * DD + e] * W[(size_t)e * DD + d];
    M[which * 2 * DD + o * DD + d] = s;
}

__global__ void uv_kernel(const float* __restrict__ x2, const float* __restrict__ cnt,
                          float* __restrict__ uv) {
    __shared__ float cs[NN];
    const int b = blockIdx.x, t = threadIdx.x;
    if (t < NN) cs[t] = cnt[(size_t)b * NN + t];
    __syncthreads();
    const float* xb = x2 + (size_t)b * NN * DD;
    float u = 0.f, v = 0.f;
    #pragma unroll 4
    for (int i = 0; i < NN; ++i) {
        float val = xb[(size_t)i * DD + t];
        v += val;
        u += cs[i] * val;
    }
    uv[(size_t)b * 2 * DD + t]      = u * (1.f / (3.f * (float)NN));
    uv[(size_t)b * 2 * DD + DD + t] = v * (1.f / (float)NN);
}

__global__ void final_kernel(const float* __restrict__ uv, const float* __restrict__ M,
                             const float* __restrict__ wc, const float* __restrict__ b3l,
                             const float* __restrict__ bc, float* __restrict__ out) {
    const int b = blockIdx.x, t = threadIdx.x;
    const float u = uv[(size_t)b * 2 * DD + t];
    const float v = uv[(size_t)b * 2 * DD + DD + t];
    const float bl = b3l[t];
    float s0 = u * M[t]      + v * M[2 * DD + t] + wc[t] * bl;
    float s1 = u * M[DD + t] + v * M[3 * DD + t] + wc[DD + t] * bl;
    #pragma unroll
    for (int off = 16; off; off >>= 1) {
        s0 += __shfl_xor_sync(0xffffffffu, s0, off);
        s1 += __shfl_xor_sync(0xffffffffu, s1, off);
    }
    __shared__ float r0[16], r1[16];
    const int warp = t >> 5, lane = t & 31;
    if (lane == 0) { r0[warp] = s0; r1[warp] = s1; }
    __syncthreads();
    if (t == 0) {
        float t0 = 0.f, t1 = 0.f;
        #pragma unroll
        for (int w = 0; w < 16; ++w) { t0 += r0[w]; t1 += r1[w]; }
        out[b * 2 + 0] = t0 + bc[0];
        out[b * 2 + 1] = t1 + bc[1];
    }
}

// ---------------------------------------------------------------------------
extern "C" void kernel_launch(void* const* d_in, const int* in_sizes, int n_in,
                              void* d_out, int out_size) {
    const float* enc = (const float*)d_in[0];
    const float* w1l = (const float*)d_in[1];
    const float* b1l = (const float*)d_in[2];
    const float* w1r = (const float*)d_in[3];
    const float* w2l = (const float*)d_in[4];
    const float* b2l = (const float*)d_in[5];
    const float* w2r = (const float*)d_in[6];
    const float* w3l = (const float*)d_in[7];
    const float* b3l = (const float*)d_in[8];
    const float* w3r = (const float*)d_in[9];
    const float* wc  = (const float*)d_in[10];
    const float* bc  = (const float*)d_in[11];
    float* out = (float*)d_out;

    float *x1, *x2, *cntp, *uvp, *Mp;
    int* idxp;
    cudaGetSymbolAddress((void**)&x1,   g_x1);
    cudaGetSymbolAddress((void**)&x2,   g_x2);
    cudaGetSymbolAddress((void**)&idxp, g_idx);
    cudaGetSymbolAddress((void**)&cntp, g_cnt);
    cudaGetSymbolAddress((void**)&uvp,  g_uv);
    cudaGetSymbolAddress((void**)&Mp,   g_M);

    // kNN graph
    knn_kernel<<<dim3(2, BB), 256>>>(enc, idxp);
    cnt_kernel<<<BB, NN>>>(idxp, cntp);

    // layers 1-2 on tensor cores via mma.sync tf32 (gather fused into producer)
    sage_mma<<<dim3(4, BB), 256>>>(enc, idxp, w1l, w1r, b1l, x1, 1);
    sage_mma<<<dim3(4, BB), 256>>>(x1,  idxp, w2l, w2r, b2l, x2, 1);

    // layer 3 + mean-pool + classifier, algebraically collapsed
    mlmr_kernel<<<4, DD>>>(wc, w3l, w3r, Mp);
    uv_kernel<<<BB, DD>>>(x2, cntp, uvp);
    final_kernel<<<BB, DD>>>(uvp, Mp, wc, b3l, bc, out);
}